// round 13
// baseline (speedup 1.0000x reference)
#include <cuda_runtime.h>

typedef unsigned long long u64;

#define CH_IN 32
#define CH_Y  16
#define WDIM  256
#define PLANE (256*256)
#define NTHR  128    // 1 row/CTA: thread t -> quad qi=t>>1 (px 4qi..4qi+3), cy-half cyh=t&1

__device__ __forceinline__ u64 pack2(float lo, float hi) {
    u64 r; asm("mov.b64 %0, {%1, %2};" : "=l"(r) : "f"(lo), "f"(hi)); return r;
}
__device__ __forceinline__ u64 dup2(float w) {
    u64 r; asm("mov.b64 %0, {%1, %1};" : "=l"(r) : "f"(w)); return r;
}
__device__ __forceinline__ void ffma2(u64& d, u64 a, u64 b) {
    asm("fma.rn.f32x2 %0, %1, %2, %0;" : "+l"(d) : "l"(a), "l"(b));
}
__device__ __forceinline__ u64 mul2(u64 a, u64 b) {
    u64 r; asm("mul.rn.f32x2 %0, %1, %2;" : "=l"(r) : "l"(a), "l"(b)); return r;
}
__device__ __forceinline__ float lo2(u64 v) {
    float lo, hi; asm("mov.b64 {%0, %1}, %2;" : "=f"(lo), "=f"(hi) : "l"(v)); return lo;
}
__device__ __forceinline__ float hi2(u64 v) {
    float lo, hi; asm("mov.b64 {%0, %1}, %2;" : "=f"(lo), "=f"(hi) : "l"(v)); return hi;
}

__global__ __launch_bounds__(NTHR, 4)
void cross_modal_attn_kernel(
    const float* __restrict__ c,  const float* __restrict__ p,
    const float* __restrict__ Wq, const float* __restrict__ bq,
    const float* __restrict__ Wk, const float* __restrict__ bk,
    const float* __restrict__ Wv, const float* __restrict__ bv,
    const float* __restrict__ Wy, const float* __restrict__ by,
    float* __restrict__ out)
{
    const int tid  = threadIdx.x;
    const int lane = tid & 31, warp = tid >> 5;
    const int cyh  = tid & 1;          // channel half: cy in [8*cyh, 8*cyh+8)
    const int qi   = tid >> 1;         // pixel quad 0..63 (px 4qi..4qi+3)
    const int h    = blockIdx.x;
    const int b    = blockIdx.y;

    __shared__ float4 sWq[CH_Y*8], sWk[CH_Y*8], sWv[CH_Y*8];  // [cy][8 float4]
    __shared__ float4 sWy[CH_IN*4];                            // [co][4 float4]
    __shared__ float sbq[CH_Y], sbk[CH_Y], sbv[CH_Y], sby[CH_IN];
    __shared__ float sred[2][8][5];    // [cyh][cy8][warp] (+pad)
    __shared__ float sfin[2][8];

    {
        float* dWq = (float*)sWq; float* dWk = (float*)sWk;
        float* dWv = (float*)sWv; float* dWy = (float*)sWy;
        for (int i = tid; i < CH_Y*CH_IN; i += NTHR) {
            dWq[i] = Wq[i]; dWk[i] = Wk[i]; dWv[i] = Wv[i]; dWy[i] = Wy[i];
        }
    }
    if (tid < CH_Y)  { sbq[tid] = bq[tid]; sbk[tid] = bk[tid]; sbv[tid] = bv[tid]; }
    if (tid < CH_IN) { sby[tid] = by[tid]; }
    __syncthreads();

    const size_t base_in4  = (((size_t)b * CH_IN) * PLANE + (size_t)h * WDIM) / 4 + qi;
    const size_t base_out4 = (((size_t)b * (2*CH_IN)) * PLANE + (size_t)h * WDIM) / 4 + qi;
    const float4* p4 = (const float4*)p;
    const float4* c4 = (const float4*)c;
    float4* o4 = (float4*)out;
    float2* o2 = (float2*)out;
    const size_t cs4 = PLANE / 4;
    const int cb = cyh * 8;            // my first cy

    // ---- Phase K: k for my 8 channels over 4 chunks of 8 input channels ----
    u64 kl[8], kh[8];
#pragma unroll
    for (int i = 0; i < 8; i++) { kl[i] = dup2(sbk[cb+i]); kh[i] = kl[i]; }
#pragma unroll
    for (int ch4 = 0; ch4 < 4; ch4++) {
        u64 xl[8], xh[8];
#pragma unroll
        for (int j = 0; j < 8; j++) {
            float4 v4 = __ldg(p4 + base_in4 + (size_t)(ch4*8 + j) * cs4);
            xl[j] = pack2(v4.x, v4.y); xh[j] = pack2(v4.z, v4.w);
        }
#pragma unroll
        for (int i = 0; i < 8; i++) {
#pragma unroll
            for (int j4 = 0; j4 < 2; j4++) {
                const float4 w = sWk[(cb+i)*8 + ch4*2 + j4];
                u64 w0 = dup2(w.x), w1 = dup2(w.y), w2 = dup2(w.z), w3 = dup2(w.w);
                ffma2(kl[i], w0, xl[4*j4+0]); ffma2(kh[i], w0, xh[4*j4+0]);
                ffma2(kl[i], w1, xl[4*j4+1]); ffma2(kh[i], w1, xh[4*j4+1]);
                ffma2(kl[i], w2, xl[4*j4+2]); ffma2(kh[i], w2, xh[4*j4+2]);
                ffma2(kl[i], w3, xl[4*j4+3]); ffma2(kh[i], w3, xh[4*j4+3]);
            }
        }
    }

    // ---- Phase Q: q for my 8 channels + concat copy (pair splits the stores) ----
    u64 al[8], ah[8];
#pragma unroll
    for (int i = 0; i < 8; i++) { al[i] = dup2(sbq[cb+i]); ah[i] = al[i]; }
#pragma unroll
    for (int ch4 = 0; ch4 < 4; ch4++) {
        u64 xl[8], xh[8];
#pragma unroll
        for (int j = 0; j < 8; j++) {
            float4 v4 = __ldcs(c4 + base_in4 + (size_t)(ch4*8 + j) * cs4);
            // concat: even thread stores px 0-1 of the quad, odd stores px 2-3
            float2 st; 
            if (cyh == 0) { st.x = v4.x; st.y = v4.y; } else { st.x = v4.z; st.y = v4.w; }
            const size_t oi2 = (((size_t)b*(2*CH_IN) + (CH_IN + ch4*8 + j)) * PLANE
                                + (size_t)h * WDIM) / 2 + qi*2 + cyh;
            __stcs(o2 + oi2, st);
            xl[j] = pack2(v4.x, v4.y); xh[j] = pack2(v4.z, v4.w);
        }
#pragma unroll
        for (int i = 0; i < 8; i++) {
#pragma unroll
            for (int j4 = 0; j4 < 2; j4++) {
                const float4 w = sWq[(cb+i)*8 + ch4*2 + j4];
                u64 w0 = dup2(w.x), w1 = dup2(w.y), w2 = dup2(w.z), w3 = dup2(w.w);
                ffma2(al[i], w0, xl[4*j4+0]); ffma2(ah[i], w0, xh[4*j4+0]);
                ffma2(al[i], w1, xl[4*j4+1]); ffma2(ah[i], w1, xh[4*j4+1]);
                ffma2(al[i], w2, xl[4*j4+2]); ffma2(ah[i], w2, xh[4*j4+2]);
                ffma2(al[i], w3, xl[4*j4+3]); ffma2(ah[i], w3, xh[4*j4+3]);
            }
        }
    }

    // ---- t = exp(q*k); no max-subtraction (|q*k| <~ 12, fp32-safe) ----
#pragma unroll
    for (int i = 0; i < 8; i++) {
        u64 ql = mul2(al[i], kl[i]);
        u64 qh = mul2(ah[i], kh[i]);
        al[i] = pack2(__expf(lo2(ql)), __expf(hi2(ql)));
        ah[i] = pack2(__expf(lo2(qh)), __expf(hi2(qh)));
    }

    // ---- softmax sum over the row: 4 own px -> parity-strided shfl -> smem ----
#pragma unroll
    for (int i = 0; i < 8; i++) {
        float s = lo2(al[i]) + hi2(al[i]) + lo2(ah[i]) + hi2(ah[i]);
#pragma unroll
        for (int o = 2; o <= 16; o <<= 1) s += __shfl_xor_sync(0xffffffffu, s, o);
        if ((lane >> 1) == 0) sred[cyh][i][warp] = s;   // lanes 0,1 (lane&1==cyh)
    }
    __syncthreads();
    if (tid < 16) {
        const int hh = tid >> 3, cc = tid & 7;
        float s = sred[hh][cc][0] + sred[hh][cc][1] + sred[hh][cc][2] + sred[hh][cc][3];
        sfin[hh][cc] = 1.0f / s;
    }
    __syncthreads();

    // ---- Phase V: reload p (L2/L1-hot), v for my 8 channels ----
    u64 vl[8], vh[8];
#pragma unroll
    for (int i = 0; i < 8; i++) { vl[i] = dup2(sbv[cb+i]); vh[i] = vl[i]; }
#pragma unroll
    for (int ch4 = 0; ch4 < 4; ch4++) {
        u64 xl[8], xh[8];
#pragma unroll
        for (int j = 0; j < 8; j++) {
            float4 v4 = __ldg(p4 + base_in4 + (size_t)(ch4*8 + j) * cs4);
            xl[j] = pack2(v4.x, v4.y); xh[j] = pack2(v4.z, v4.w);
        }
#pragma unroll
        for (int i = 0; i < 8; i++) {
#pragma unroll
            for (int j4 = 0; j4 < 2; j4++) {
                const float4 w = sWv[(cb+i)*8 + ch4*2 + j4];
                u64 w0 = dup2(w.x), w1 = dup2(w.y), w2 = dup2(w.z), w3 = dup2(w.w);
                ffma2(vl[i], w0, xl[4*j4+0]); ffma2(vh[i], w0, xh[4*j4+0]);
                ffma2(vl[i], w1, xl[4*j4+1]); ffma2(vh[i], w1, xh[4*j4+1]);
                ffma2(vl[i], w2, xl[4*j4+2]); ffma2(vh[i], w2, xh[4*j4+2]);
                ffma2(vl[i], w3, xl[4*j4+3]); ffma2(vh[i], w3, xh[4*j4+3]);
            }
        }
    }

    // y = t * rinv * v (my 8 channels)
#pragma unroll
    for (int i = 0; i < 8; i++) {
        const u64 ri = dup2(sfin[cyh][i]);
        al[i] = mul2(mul2(al[i], ri), vl[i]);
        ah[i] = mul2(mul2(ah[i], ri), vh[i]);
    }

    // ---- exchange with partner lane: full 16-cy y for the quad ----
    u64 yl[16], yh[16];
#pragma unroll
    for (int i = 0; i < 8; i++) {
        yl[cb + i] = al[i];
        yh[cb + i] = ah[i];
    }
    const int ob = (1 - cyh) * 8;      // partner's base
#pragma unroll
    for (int i = 0; i < 8; i++) {
        yl[ob + i] = __shfl_xor_sync(0xffffffffu, al[i], 1);
        yh[ob + i] = __shfl_xor_sync(0xffffffffu, ah[i], 1);
    }

    // ---- Phase O: output conv; this thread does co = 2*i + cyh ----
#pragma unroll
    for (int i = 0; i < 16; i++) {
        const int co = 2*i + cyh;
        u64 accl = dup2(sby[co]), acch = accl;
#pragma unroll
        for (int j4 = 0; j4 < 4; j4++) {
            const float4 w = sWy[co*4 + j4];
            u64 w0 = dup2(w.x), w1 = dup2(w.y), w2 = dup2(w.z), w3 = dup2(w.w);
            ffma2(accl, w0, yl[4*j4+0]); ffma2(acch, w0, yh[4*j4+0]);
            ffma2(accl, w1, yl[4*j4+1]); ffma2(acch, w1, yh[4*j4+1]);
            ffma2(accl, w2, yl[4*j4+2]); ffma2(acch, w2, yh[4*j4+2]);
            ffma2(accl, w3, yl[4*j4+3]); ffma2(acch, w3, yh[4*j4+3]);
        }
        float4 w4;
        w4.x = lo2(accl); w4.y = hi2(accl); w4.z = lo2(acch); w4.w = hi2(acch);
        __stcs(o4 + base_out4 + (size_t)co * cs4, w4);
    }
}

extern "C" void kernel_launch(void* const* d_in, const int* in_sizes, int n_in,
                              void* d_out, int out_size)
{
    const float* c  = (const float*)d_in[0];
    const float* p  = (const float*)d_in[1];
    const float* Wq = (const float*)d_in[2];
    const float* bq = (const float*)d_in[3];
    const float* Wk = (const float*)d_in[4];
    const float* bk = (const float*)d_in[5];
    const float* Wv = (const float*)d_in[6];
    const float* bv = (const float*)d_in[7];
    const float* Wy = (const float*)d_in[8];
    const float* by = (const float*)d_in[9];
    float* out = (float*)d_out;

    dim3 grid(WDIM, 16);   // (256, 16) = 4096 CTAs, one row each
    dim3 block(NTHR);      // 64 quads x 2 channel-halves
    cross_modal_attn_kernel<<<grid, block>>>(c, p, Wq, bq, Wk, bk, Wv, bv, Wy, by, out);
}

// round 16
// speedup vs baseline: 1.0226x; 1.0226x over previous
#include <cuda_runtime.h>

typedef unsigned long long u64;

#define CH_IN 32
#define CH_Y  16
#define WDIM  256
#define PLANE (256*256)
#define NTHR  128           // one row: thread t owns w = 2t, 2t+1

__device__ __forceinline__ u64 pack2(float lo, float hi) {
    u64 r; asm("mov.b64 %0, {%1, %2};" : "=l"(r) : "f"(lo), "f"(hi)); return r;
}
__device__ __forceinline__ u64 dup2(float w) {
    u64 r; asm("mov.b64 %0, {%1, %1};" : "=l"(r) : "f"(w)); return r;
}
__device__ __forceinline__ void ffma2(u64& d, u64 a, u64 b) {
    asm("fma.rn.f32x2 %0, %1, %2, %0;" : "+l"(d) : "l"(a), "l"(b));
}
__device__ __forceinline__ float lo2(u64 v) {
    float lo, hi; asm("mov.b64 {%0, %1}, %2;" : "=f"(lo), "=f"(hi) : "l"(v)); return lo;
}
__device__ __forceinline__ float hi2(u64 v) {
    float lo, hi; asm("mov.b64 {%0, %1}, %2;" : "=f"(lo), "=f"(hi) : "l"(v)); return hi;
}
// horizontal sum of interleaved partials + bias
__device__ __forceinline__ float hsum_b(u64 v, float b) {
    return b + lo2(v) + hi2(v);
}

__global__ __launch_bounds__(NTHR, 4)
void cross_modal_attn_kernel(
    const float* __restrict__ c,  const float* __restrict__ p,
    const float* __restrict__ Wq, const float* __restrict__ bq,
    const float* __restrict__ Wk, const float* __restrict__ bk,
    const float* __restrict__ Wv, const float* __restrict__ bv,
    const float* __restrict__ Wy, const float* __restrict__ by,
    float* __restrict__ out)
{
    const int tid  = threadIdx.x;      // 0..127; pixels w=2tid, 2tid+1
    const int lane = tid & 31, warp = tid >> 5;
    const int h    = blockIdx.x;
    const int b    = blockIdx.y;

    // q/k/v weights row-major [cy][ci/4] (ci-pairs contiguous -> dup-free FFMA2)
    __shared__ float4 sWq[CH_Y*8], sWk[CH_Y*8], sWv[CH_Y*8];
    // y weights TRANSPOSED [cy][co/4] (co-pairs contiguous)
    __shared__ float4 sWyT[CH_Y*8];
    __shared__ float  sbq[CH_Y], sbk[CH_Y], sbv[CH_Y];
    __shared__ float2 sby2[CH_IN/2];   // by co-pairs
    __shared__ float  sred[CH_Y][5];   // [channel][warp], 4 warps + pad
    __shared__ float  sfin[CH_Y];

    {
        float* dWq = (float*)sWq; float* dWk = (float*)sWk; float* dWv = (float*)sWv;
        float* dWyT = (float*)sWyT;
        for (int i = tid; i < CH_Y*CH_IN; i += NTHR) {
            dWq[i] = Wq[i]; dWk[i] = Wk[i]; dWv[i] = Wv[i];
            // transpose Wy: global Wy[o*CH_Y + cidx] -> sWyT[cidx*CH_IN + o]
            const int cidx = i >> 5, o = i & 31;   // i = cidx*32 + o
            dWyT[i] = Wy[o*CH_Y + cidx];
        }
    }
    if (tid < CH_Y)    { sbq[tid] = bq[tid]; sbk[tid] = bk[tid]; sbv[tid] = bv[tid]; }
    if (tid < CH_IN/2) { sby2[tid] = make_float2(by[2*tid], by[2*tid+1]); }
    __syncthreads();

    const size_t base_in2  = (((size_t)b * CH_IN) * PLANE + (size_t)h * WDIM) / 2 + tid;
    const size_t base_out2 = (((size_t)b * (2*CH_IN)) * PLANE + (size_t)h * WDIM) / 2 + tid;
    const float2* p2 = (const float2*)p;
    const float2* c2 = (const float2*)c;
    float2* o2 = (float2*)out;
    const size_t cs2 = PLANE / 2;

    // ================= Phase A: c -> q scalars + concat copy =================
    float q0[CH_Y], q1[CH_Y];          // q per (cy, px)
#pragma unroll
    for (int ch = 0; ch < 2; ch++) {
        // batched loads (MLP=16), immediate concat store
        float2 v2[16];
#pragma unroll
        for (int j = 0; j < 16; j++)
            v2[j] = __ldcs(c2 + base_in2 + (size_t)(ch*16 + j) * cs2);
#pragma unroll
        for (int j = 0; j < 16; j++)
            __stcs(o2 + base_out2 + (size_t)(CH_IN + ch*16 + j) * cs2, v2[j]);
        // repack to ci-pairs per pixel
        u64 x0[8], x1[8];
#pragma unroll
        for (int j = 0; j < 8; j++) {
            x0[j] = pack2(v2[2*j].x, v2[2*j+1].x);
            x1[j] = pack2(v2[2*j].y, v2[2*j+1].y);
        }
#pragma unroll
        for (int cy = 0; cy < CH_Y; cy++) {
            u64 t0 = 0ULL, t1 = 0ULL;
#pragma unroll
            for (int j4 = 0; j4 < 4; j4++) {
                const float4 w = sWq[cy*8 + ch*4 + j4];
                const u64 wa = pack2(w.x, w.y), wb = pack2(w.z, w.w);
                ffma2(t0, wa, x0[2*j4]); ffma2(t0, wb, x0[2*j4+1]);
                ffma2(t1, wa, x1[2*j4]); ffma2(t1, wb, x1[2*j4+1]);
            }
            if (ch == 0) { q0[cy] = hsum_b(t0, sbq[cy]); q1[cy] = hsum_b(t1, sbq[cy]); }
            else         { q0[cy] += lo2(t0) + hi2(t0);  q1[cy] += lo2(t1) + hi2(t1); }
        }
    }

    // ============ Phase B: load all p, repack to ci-pairs (kept live) ========
    u64 xp0[16], xp1[16];
#pragma unroll
    for (int ch = 0; ch < 2; ch++) {
        float2 v2[16];
#pragma unroll
        for (int j = 0; j < 16; j++)
            v2[j] = __ldcs(p2 + base_in2 + (size_t)(ch*16 + j) * cs2);
#pragma unroll
        for (int j = 0; j < 8; j++) {
            xp0[ch*8 + j] = pack2(v2[2*j].x, v2[2*j+1].x);
            xp1[ch*8 + j] = pack2(v2[2*j].y, v2[2*j+1].y);
        }
    }

    // ===== Phase C: k per cy on the fly, t = exp(q*k) in place (scalars) =====
    // no max-subtraction: |q*k| <~ 12, fp32 exp safe; normalization identical
#pragma unroll
    for (int cy = 0; cy < CH_Y; cy++) {
        u64 t0 = 0ULL, t1 = 0ULL;
#pragma unroll
        for (int j4 = 0; j4 < 8; j4++) {
            const float4 w = sWk[cy*8 + j4];
            const u64 wa = pack2(w.x, w.y), wb = pack2(w.z, w.w);
            ffma2(t0, wa, xp0[2*j4]); ffma2(t0, wb, xp0[2*j4+1]);
            ffma2(t1, wa, xp1[2*j4]); ffma2(t1, wb, xp1[2*j4+1]);
        }
        q0[cy] = __expf(q0[cy] * hsum_b(t0, sbk[cy]));
        q1[cy] = __expf(q1[cy] * hsum_b(t1, sbk[cy]));
    }

    // ================= Phase D: softmax sum over the row ====================
#pragma unroll
    for (int cy = 0; cy < CH_Y; cy++) {
        float s = q0[cy] + q1[cy];
#pragma unroll
        for (int o = 16; o; o >>= 1) s += __shfl_xor_sync(0xffffffffu, s, o);
        if (lane == 0) sred[cy][warp] = s;
    }
    __syncthreads();
    if (tid < CH_Y) {
        float s = sred[tid][0] + sred[tid][1] + sred[tid][2] + sred[tid][3];
        sfin[tid] = 1.0f / s;
    }
    __syncthreads();

    // ====== Phase E: v per cy on the fly (xp still live), y scalars =========
#pragma unroll
    for (int cy = 0; cy < CH_Y; cy++) {
        u64 t0 = 0ULL, t1 = 0ULL;
#pragma unroll
        for (int j4 = 0; j4 < 8; j4++) {
            const float4 w = sWv[cy*8 + j4];
            const u64 wa = pack2(w.x, w.y), wb = pack2(w.z, w.w);
            ffma2(t0, wa, xp0[2*j4]); ffma2(t0, wb, xp0[2*j4+1]);
            ffma2(t1, wa, xp1[2*j4]); ffma2(t1, wb, xp1[2*j4+1]);
        }
        const float ri = sfin[cy];
        q0[cy] = q0[cy] * ri * hsum_b(t0, sbv[cy]);
        q1[cy] = q1[cy] * ri * hsum_b(t1, sbv[cy]);
    }

    // ====== Phase F: output conv 16->32, channel-packed (co-pairs) ==========
    // accO_px[j] = (out[2j], out[2j+1]) for pixel px
    u64 accO0[CH_IN/2], accO1[CH_IN/2];
#pragma unroll
    for (int j = 0; j < CH_IN/2; j++) {
        const float2 bb = sby2[j];
        const u64 bi = pack2(bb.x, bb.y);
        accO0[j] = bi; accO1[j] = bi;
    }
#pragma unroll
    for (int cy = 0; cy < CH_Y; cy++) {
        const u64 y0 = dup2(q0[cy]);
        const u64 y1 = dup2(q1[cy]);
#pragma unroll
        for (int j4 = 0; j4 < 8; j4++) {
            const float4 w = sWyT[cy*8 + j4];
            const u64 wa = pack2(w.x, w.y), wb = pack2(w.z, w.w);
            ffma2(accO0[2*j4],   wa, y0); ffma2(accO0[2*j4+1], wb, y0);
            ffma2(accO1[2*j4],   wa, y1); ffma2(accO1[2*j4+1], wb, y1);
        }
    }
#pragma unroll
    for (int j = 0; j < CH_IN/2; j++) {
        float2 s0; s0.x = lo2(accO0[j]); s0.y = lo2(accO1[j]);   // co = 2j
        float2 s1; s1.x = hi2(accO0[j]); s1.y = hi2(accO1[j]);   // co = 2j+1
        __stcs(o2 + base_out2 + (size_t)(2*j)   * cs2, s0);
        __stcs(o2 + base_out2 + (size_t)(2*j+1) * cs2, s1);
    }
}

extern "C" void kernel_launch(void* const* d_in, const int* in_sizes, int n_in,
                              void* d_out, int out_size)
{
    const float* c  = (const float*)d_in[0];
    const float* p  = (const float*)d_in[1];
    const float* Wq = (const float*)d_in[2];
    const float* bq = (const float*)d_in[3];
    const float* Wk = (const float*)d_in[4];
    const float* bk = (const float*)d_in[5];
    const float* Wv = (const float*)d_in[6];
    const float* bv = (const float*)d_in[7];
    const float* Wy = (const float*)d_in[8];
    const float* by = (const float*)d_in[9];
    float* out = (float*)d_out;

    dim3 grid(WDIM, 16);   // (256, 16) = 4096 CTAs, one row each
    dim3 block(NTHR);      // 128 threads = one row of pixel pairs
    cross_modal_attn_kernel<<<grid, block>>>(c, p, Wq, bq, Wk, bk, Wv, bv, Wy, by, out);
}